// round 6
// baseline (speedup 1.0000x reference)
#include <cuda_runtime.h>
#include <math.h>

#define TPB 128
#define TI  8
#define MAX_BLOCKS 32768

// Per-block partial sums (x=R^2, y=energy, z=area) and a self-resetting ticket.
__device__ float4       g_part[MAX_BLOCKS];
__device__ unsigned int g_ticket = 0;

__device__ __forceinline__ int clampi(int v, int hi) {
    return v < 0 ? 0 : (v > hi ? hi : v);
}

// Shared-memory tiled node-parallel gather for the P1-triangle elasticity loss
// on _grid_mesh(G). Block = 8 rows x 128 cols of nodes. u_pred staged in U
// (clamped halo), err = u_pred - u_true staged in Er. Each thread walks its
// column with a 3x3 register window (5 LDS.64 per node). Interior nodes use
// the collapsed constant-coefficient stencil (h cancels); boundary nodes use
// the verified general per-cell path with coords.
__global__ void __launch_bounds__(TPB, 8) pino_tile_kernel(
    const float2* __restrict__ up, const float2* __restrict__ ut,
    const float2* __restrict__ coords, float* __restrict__ out,
    int g, int nblocks, float h2)
{
    const float F   = 1.0f / (1.0f - 0.3f * 0.3f);  // plane-stress factor
    const float NU  = 0.3f;
    const float FG  = F * 0.35f;                    // F*(1-nu)/2
    const float CCR = 0.325f * F;                   // 0.5*(F*NU + FG)

    __shared__ float2 U [TI + 2][TPB + 2];  // rows i0-1..i0+TI, cols j0-1..j0+TPB (clamped)
    __shared__ float2 Er[TI + 1][TPB + 1];  // err rows i0..i0+TI, cols j0..j0+TPB (clamped)

    const int tid = threadIdx.x;
    const int i0  = blockIdx.y * TI;
    const int j0  = blockIdx.x * TPB;
    const int j   = j0 + tid;
    const int ghi = g - 1;

    // ---- stage u_pred tile (coalesced, clamped halo) ----
    #pragma unroll
    for (int r = 0; r < TI + 2; r++) {
        const int gr = clampi(i0 - 1 + r, ghi);
        const float2* __restrict__ src = up + (size_t)gr * g;
        U[r][tid] = src[clampi(j0 - 1 + tid, ghi)];
        if (tid < 2)
            U[r][TPB + tid] = src[clampi(j0 - 1 + TPB + tid, ghi)];
    }
    __syncthreads();

    // ---- stage err tile: Er = U - u_true ----
    #pragma unroll
    for (int r = 0; r < TI + 1; r++) {
        const int gr = clampi(i0 + r, ghi);
        const float2* __restrict__ tsrc = ut + (size_t)gr * g;
        {
            float2 t = tsrc[clampi(j0 + tid, ghi)];
            float2 u = U[r + 1][tid + 1];
            Er[r][tid] = make_float2(u.x - t.x, u.y - t.y);
        }
        if (tid == 0) {
            float2 t = tsrc[clampi(j0 + TPB, ghi)];
            float2 u = U[r + 1][TPB + 1];
            Er[r][TPB] = make_float2(u.x - t.x, u.y - t.y);
        }
    }
    __syncthreads();

    float sR2 = 0.f, sEn = 0.f, sA = 0.f;

    if (j < g) {
        const int c = tid + 1;
        // 3x3 register window over U (rows i-1, i, i+1)
        float2 nW = U[0][c - 1], n0 = U[0][c], nE = U[0][c + 1];
        float2 wW = U[1][c - 1], w0 = U[1][c], wE = U[1][c + 1];
        // err window (rows i, i+1) x (cols j, j+1)
        float2 e00 = Er[0][tid], e01 = Er[0][tid + 1];

        #pragma unroll
        for (int k = 0; k < TI; k++) {
            const int i = i0 + k;
            if (i >= g) break;
            float2 vW = U[k + 2][c - 1], v0 = U[k + 2][c], vE = U[k + 2][c + 1];
            float2 es0 = Er[k + 1][tid], es1 = Er[k + 1][tid + 1];

            if (i > 0 && i + 1 < g && j > 0 && j + 1 < g) {
                // ---------- interior: collapsed constant-coefficient stencil ----------
                const float Xc = 2.f*w0.x - wE.x - wW.x - n0.x - v0.x + nE.x + vW.x;
                const float Yc = 2.f*w0.y - wE.y - wW.y - n0.y - v0.y + nE.y + vW.y;
                const float Rx = F  * (2.f*w0.x - n0.x - v0.x)
                               + FG * (2.f*w0.x - wE.x - wW.x) + CCR * Yc;
                const float Ry = F  * (2.f*w0.y - wE.y - wW.y)
                               + FG * (2.f*w0.y - n0.y - v0.y) + CCR * Xc;
                sR2 += Rx*Rx + Ry*Ry;

                // energy of owned cell (i,j), h-free form
                float e0 = es0.x - e00.x;
                float e1 = e01.y - e00.y;
                float e2 = (e01.x - e00.x) + (es0.y - e00.y);
                float en = F * (e0*e0 + 2.f*NU*e0*e1 + e1*e1) + FG * e2*e2;
                e0 = es1.x - e01.x;
                e1 = es1.y - es0.y;
                e2 = (es1.x - es0.x) + (es1.y - e01.y);
                en += F * (e0*e0 + 2.f*NU*e0*e1 + e1*e1) + FG * e2*e2;
                sEn += 0.5f * en;
                sA  += h2;
            } else {
                // ---------- general boundary path (verified R1/R3) ----------
                const int ipn = (i + 1 < g) ? i + 1 : i;
                const int imn = (i > 0)     ? i - 1 : i;
                const int jpn = (j + 1 < g) ? j + 1 : j;
                const int jmn = (j > 0)     ? j - 1 : j;
                const float xi  = coords[i].y;
                const float dxp = coords[ipn].y - xi;
                const float dxm = xi - coords[imn].y;
                const float yj  = coords[j].y;
                const float dyp = coords[jpn].y - yj;
                const float dym = yj - coords[jmn].y;
                const float pp  = (i + 1 < g) ? __fdividef(1.f, dxp) : 0.f;
                const float pm  = (i > 0)     ? __fdividef(1.f, dxm) : 0.f;
                const float qp  = (j + 1 < g) ? __fdividef(1.f, dyp) : 0.f;
                const float qm  = (j > 0)     ? __fdividef(1.f, dym) : 0.f;

                const float a1 = 0.5f * dxp * dyp;
                const float a2 = 0.5f * dxp * dym;
                const float a3 = 0.5f * dxm * dyp;
                const float a4 = 0.5f * dxm * dym;

                // clamped-neighbor window values
                const float2 u00 = w0, uE = wE, uW = wW;
                const float2 uN  = n0, uNE = nE;
                const float2 uS  = v0, uSW = vW;

                float e0, e1, e2, s0, s1, s2;
                float Rx = 0.f, Ry = 0.f;
#define SIG_() do { s0 = F*(e0 + NU*e1); s1 = F*(NU*e0 + e1); s2 = FG*e2; } while (0)
                // C1: cell (i,j) tri1, slot a: (u00, uE, uS)
                e0 = pp*(uS.x - u00.x);
                e1 = qp*(uE.y - u00.y);
                e2 = qp*(uE.x - u00.x) + pp*(uS.y - u00.y);
                SIG_();
                Rx += a1*(-pp*s0 - qp*s2);
                Ry += a1*(-qp*s1 - pp*s2);
                // C2: cell (i,j-1) tri1, slot b: (uW, u00, uSW)
                e0 = pp*(uSW.x - uW.x);
                e1 = qm*(u00.y - uW.y);
                e2 = qm*(u00.x - uW.x) + pp*(uSW.y - uW.y);
                SIG_();
                Rx += a2*(qm*s2);
                Ry += a2*(qm*s1);
                // C3: cell (i,j-1) tri2, slot b: (u00, uS, uSW)
                e0 = pp*(uS.x - u00.x);
                e1 = qm*(uS.y - uSW.y);
                e2 = qm*(uS.x - uSW.x) + pp*(uS.y - u00.y);
                SIG_();
                Rx -= a2*(pp*s0);
                Ry -= a2*(pp*s2);
                // C4: cell (i-1,j) tri1, slot c: (uN, uNE, u00)
                e0 = pm*(u00.x - uN.x);
                e1 = qp*(uNE.y - uN.y);
                e2 = qp*(uNE.x - uN.x) + pm*(u00.y - uN.y);
                SIG_();
                Rx += a3*(pm*s0);
                Ry += a3*(pm*s2);
                // C5: cell (i-1,j) tri2, slot c: (uNE, uE, u00)
                e0 = pm*(uE.x - uNE.x);
                e1 = qp*(uE.y - u00.y);
                e2 = qp*(uE.x - u00.x) + pm*(uE.y - uNE.y);
                SIG_();
                Rx -= a3*(qp*s2);
                Ry -= a3*(qp*s1);
                // C6: cell (i-1,j-1) tri2, slot d: (uN, u00, uW)
                e0 = pm*(u00.x - uN.x);
                e1 = qm*(u00.y - uW.y);
                e2 = qm*(u00.x - uW.x) + pm*(u00.y - uN.y);
                SIG_();
                Rx += a4*(pm*s0 + qm*s2);
                Ry += a4*(qm*s1 + pm*s2);

                sR2 += Rx*Rx + Ry*Ry;

                // energy of owned cell (i,j)
                e0 = pp*(es0.x - e00.x);
                e1 = qp*(e01.y - e00.y);
                e2 = qp*(e01.x - e00.x) + pp*(es0.y - e00.y);
                SIG_();
                sEn += a1*(e0*s0 + e1*s1 + e2*s2);

                e0 = pp*(es1.x - e01.x);
                e1 = qp*(es1.y - es0.y);
                e2 = qp*(es1.x - es0.x) + pp*(es1.y - e01.y);
                SIG_();
                sEn += a1*(e0*s0 + e1*s1 + e2*s2);

                sA += dxp * dyp;
#undef SIG_
            }

            // shift window down one row
            nW = wW; n0 = w0; nE = wE;
            wW = vW; w0 = v0; wE = vE;
            e00 = es0; e01 = es1;
        }
    }

    // ---- block reduction ----
    #pragma unroll
    for (int o = 16; o > 0; o >>= 1) {
        sR2 += __shfl_down_sync(0xffffffffu, sR2, o);
        sEn += __shfl_down_sync(0xffffffffu, sEn, o);
        sA  += __shfl_down_sync(0xffffffffu, sA,  o);
    }
    __shared__ float sh[3][TPB / 32];
    __shared__ bool  amLast;
    const int lane = threadIdx.x & 31;
    const int wid  = threadIdx.x >> 5;
    if (lane == 0) { sh[0][wid] = sR2; sh[1][wid] = sEn; sh[2][wid] = sA; }
    __syncthreads();
    if (threadIdx.x == 0) {
        float r = 0.f, e = 0.f, a = 0.f;
        #pragma unroll
        for (int w = 0; w < TPB / 32; w++) { r += sh[0][w]; e += sh[1][w]; a += sh[2][w]; }
        const int bid = blockIdx.y * gridDim.x + blockIdx.x;
        g_part[bid] = make_float4(r, e, a, 0.f);
        __threadfence();
        unsigned int t = atomicAdd(&g_ticket, 1u);
        amLast = (t == (unsigned)(nblocks - 1));
    }
    __syncthreads();

    // ---- last block: final reduce + output + ticket reset ----
    if (amLast) {
        float r = 0.f, e = 0.f, a = 0.f;
        for (int b = threadIdx.x; b < nblocks; b += TPB) {
            float4 p = g_part[b];
            r += p.x; e += p.y; a += p.z;
        }
        #pragma unroll
        for (int o = 16; o > 0; o >>= 1) {
            r += __shfl_down_sync(0xffffffffu, r, o);
            e += __shfl_down_sync(0xffffffffu, e, o);
            a += __shfl_down_sync(0xffffffffu, a, o);
        }
        __syncthreads();
        if (lane == 0) { sh[0][wid] = r; sh[1][wid] = e; sh[2][wid] = a; }
        __syncthreads();
        if (threadIdx.x == 0) {
            r = 0.f; e = 0.f; a = 0.f;
            #pragma unroll
            for (int w = 0; w < TPB / 32; w++) { r += sh[0][w]; e += sh[1][w]; a += sh[2][w]; }
            const double N2 = 2.0 * (double)g * (double)g;
            double A = (double)a;
            if (A < 1e-30) A = 1e-30;
            out[0] = (float)(0.1 * ((double)r / N2) + 0.1 * ((double)e / A));
            g_ticket = 0;   // self-reset for next graph replay
        }
    }
}

extern "C" void kernel_launch(void* const* d_in, const int* in_sizes, int n_in,
                              void* d_out, int out_size) {
    const float2* up     = (const float2*)d_in[0];  // u_pred (N,2) f32
    const float2* ut     = (const float2*)d_in[1];  // u_true (N,2) f32
    const float2* coords = (const float2*)d_in[2];  // coords (N,2) f32
    // d_in[3] = elems — mesh structure is analytic; unused.

    int N = in_sizes[0] / 2;
    int g = (int)(sqrt((double)N) + 0.5);
    float h  = 1.0f / (float)(g - 1);
    float h2 = h * h;

    dim3 grid((g + TPB - 1) / TPB, (g + TI - 1) / TI);
    int nblocks = grid.x * grid.y;
    if (nblocks > MAX_BLOCKS) nblocks = MAX_BLOCKS;  // (never hit for G<=2048)
    pino_tile_kernel<<<grid, TPB>>>(up, ut, coords, (float*)d_out, g, nblocks, h2);
}

// round 8
// speedup vs baseline: 1.1306x; 1.1306x over previous
#include <cuda_runtime.h>
#include <math.h>

#define TPB 128
#define NPT 4
#define MAX_BLOCKS 32768

// Per-block partial sums (x=R^2, y=energy, z=area) and a self-resetting ticket.
__device__ float4       g_part[MAX_BLOCKS];
__device__ unsigned int g_ticket = 0;

__device__ __forceinline__ int clampi(int v, int hi) {
    return v < 0 ? 0 : (v > hi ? hi : v);
}

// Dual-tile node-parallel gather for the P1-triangle elasticity loss on
// _grid_mesh(G). Each thread owns TWO independent 4-node tiles in row i
// (cols j0 and j0+half). All global loads for both tiles are issued before
// any compute -> ~2x cache lines in flight per warp, one exposed DRAM
// latency per two tiles. Interior nodes use the collapsed constant-
// coefficient stencil (h cancels); boundary nodes use the verified general
// per-cell path with coords.
__global__ void __launch_bounds__(TPB, 3) pino_dual_kernel(
    const float2* __restrict__ up, const float2* __restrict__ ut,
    const float2* __restrict__ coords, float* __restrict__ out,
    int g, int nblocks, float h2, int half)
{
    const float F   = 1.0f / (1.0f - 0.3f * 0.3f);  // plane-stress factor
    const float NU  = 0.3f;
    const float FG  = F * 0.35f;                    // F*(1-nu)/2
    const float CCR = 0.325f * F;                   // 0.5*(F*NU + FG)

    const int i   = blockIdx.y;
    const int tid = threadIdx.x;
    const int ghi = g - 1;

    const int j0A = (blockIdx.x * TPB + tid) * NPT;
    const int j0s[2]  = {j0A, j0A + half};
    const int jlim[2] = {half, g};          // tile t contributes only if j0 < jlim[t]

    const int ip = (i + 1 < g) ? i + 1 : i;
    const int im = (i > 0)     ? i - 1 : i;
    const size_t rowm = (size_t)im * g;
    const size_t row  = (size_t)i  * g;
    const size_t rowp = (size_t)ip * g;
    const size_t bases[3] = {rowm, row, rowp};
    const bool irow_int = (i > 0) && (i + 1 < g);

    // u_pred rows (im,i,ip) x cols j0-1..j0+4 ; ut rows (i,ip) x cols j0..j0+4
    float2 A[2][3][6];
    float2 T[2][2][5];

    // ================= LOAD PHASE: both tiles, no intervening compute ========
    #pragma unroll
    for (int t = 0; t < 2; t++) {
        const int j0 = j0s[t];
        const bool fast = irow_int && (j0 > 0) && (j0 + NPT < g) &&
                          (((row | rowm | rowp | (size_t)j0) & 1) == 0);
        if (fast) {
            #pragma unroll
            for (int r = 0; r < 3; r++) {
                const float2* __restrict__ s = up + bases[r];
                A[t][r][0] = s[j0 - 1];
                const float4 v0 = *(const float4*)&s[j0];
                const float4 v1 = *(const float4*)&s[j0 + 2];
                A[t][r][1] = make_float2(v0.x, v0.y);
                A[t][r][2] = make_float2(v0.z, v0.w);
                A[t][r][3] = make_float2(v1.x, v1.y);
                A[t][r][4] = make_float2(v1.z, v1.w);
                A[t][r][5] = s[j0 + 4];
            }
            #pragma unroll
            for (int r = 0; r < 2; r++) {
                const float2* __restrict__ s = ut + bases[r + 1];
                const float4 t0 = *(const float4*)&s[j0];
                const float4 t1 = *(const float4*)&s[j0 + 2];
                T[t][r][0] = make_float2(t0.x, t0.y);
                T[t][r][1] = make_float2(t0.z, t0.w);
                T[t][r][2] = make_float2(t1.x, t1.y);
                T[t][r][3] = make_float2(t1.z, t1.w);
                T[t][r][4] = s[j0 + 4];
            }
        } else if (j0 < jlim[t]) {
            #pragma unroll
            for (int r = 0; r < 3; r++) {
                #pragma unroll
                for (int c = 0; c < 6; c++)
                    A[t][r][c] = up[bases[r] + clampi(j0 - 1 + c, ghi)];
            }
            #pragma unroll
            for (int r = 0; r < 2; r++) {
                #pragma unroll
                for (int c = 0; c < 5; c++)
                    T[t][r][c] = ut[bases[r + 1] + clampi(j0 + c, ghi)];
            }
        }
    }

    // ================= COMPUTE PHASE =========================================
    float sR2 = 0.f, sEn = 0.f, sA = 0.f;

    #pragma unroll
    for (int t = 0; t < 2; t++) {
        const int j0 = j0s[t];
        if (j0 >= jlim[t]) continue;
        const bool fast = irow_int && (j0 > 0) && (j0 + NPT < g) &&
                          (((row | rowm | rowp | (size_t)j0) & 1) == 0);
        if (fast) {
            #pragma unroll
            for (int k = 0; k < NPT; k++) {
                const float2 uW = A[t][1][k], u00 = A[t][1][k+1], uE = A[t][1][k+2];
                const float2 uN = A[t][0][k+1], uNE = A[t][0][k+2];
                const float2 uSW = A[t][2][k], uS = A[t][2][k+1];

                const float Xc = 2.f*u00.x - uE.x - uW.x - uN.x - uS.x + uNE.x + uSW.x;
                const float Yc = 2.f*u00.y - uE.y - uW.y - uN.y - uS.y + uNE.y + uSW.y;
                const float Rx = F  * (2.f*u00.x - uN.x - uS.x)
                               + FG * (2.f*u00.x - uE.x - uW.x) + CCR * Yc;
                const float Ry = F  * (2.f*u00.y - uE.y - uW.y)
                               + FG * (2.f*u00.y - uN.y - uS.y) + CCR * Xc;
                sR2 += Rx*Rx + Ry*Ry;

                // energy of owned cell (i,j), h-free form
                const float E0x = A[t][1][k+1].x - T[t][0][k].x,   E0y = A[t][1][k+1].y - T[t][0][k].y;
                const float EEx = A[t][1][k+2].x - T[t][0][k+1].x, EEy = A[t][1][k+2].y - T[t][0][k+1].y;
                const float ESx = A[t][2][k+1].x - T[t][1][k].x,   ESy = A[t][2][k+1].y - T[t][1][k].y;
                const float EDx = A[t][2][k+2].x - T[t][1][k+1].x, EDy = A[t][2][k+2].y - T[t][1][k+1].y;

                float e0 = ESx - E0x;
                float e1 = EEy - E0y;
                float e2 = (EEx - E0x) + (ESy - E0y);
                float en = F * (e0*e0 + 2.f*NU*e0*e1 + e1*e1) + FG * e2*e2;
                e0 = EDx - EEx;
                e1 = EDy - ESy;
                e2 = (EDx - ESx) + (EDy - EEy);
                en += F * (e0*e0 + 2.f*NU*e0*e1 + e1*e1) + FG * e2*e2;
                sEn += 0.5f * en;
                sA  += h2;
            }
        } else {
            // ---------- general boundary path (verified R1/R3/R4) ----------
            const float xi  = coords[i].y;
            const float dxp = coords[ip].y - xi;
            const float dxm = xi - coords[im].y;
            const float pp  = (i + 1 < g) ? __fdividef(1.f, dxp) : 0.f;
            const float pm  = (i > 0)     ? __fdividef(1.f, dxm) : 0.f;

            float ys[6];
            #pragma unroll
            for (int c = 0; c < 6; c++)
                ys[c] = coords[clampi(j0 - 1 + c, ghi)].y;

            float e0, e1, e2, s0, s1, s2;
#define SIG_() do { s0 = F*(e0 + NU*e1); s1 = F*(NU*e0 + e1); s2 = FG*e2; } while (0)
            #pragma unroll
            for (int k = 0; k < NPT; k++) {
                const int j = j0 + k;
                if (j < g) {
                    const float dyp = ys[k + 2] - ys[k + 1];
                    const float dym = ys[k + 1] - ys[k];
                    const float qp  = (j + 1 < g) ? __fdividef(1.f, dyp) : 0.f;
                    const float qm  = (j > 0)     ? __fdividef(1.f, dym) : 0.f;

                    const float a1 = 0.5f * dxp * dyp;
                    const float a2 = 0.5f * dxp * dym;
                    const float a3 = 0.5f * dxm * dyp;
                    const float a4 = 0.5f * dxm * dym;

                    const float2 u00 = A[t][1][k+1], uE = A[t][1][k+2], uW = A[t][1][k];
                    const float2 uN  = A[t][0][k+1], uNE = A[t][0][k+2];
                    const float2 uS  = A[t][2][k+1], uSW = A[t][2][k];

                    float Rx = 0.f, Ry = 0.f;

                    // C1: cell (i,j) tri1, slot a: (u00, uE, uS)
                    e0 = pp*(uS.x - u00.x);
                    e1 = qp*(uE.y - u00.y);
                    e2 = qp*(uE.x - u00.x) + pp*(uS.y - u00.y);
                    SIG_();
                    Rx += a1*(-pp*s0 - qp*s2);
                    Ry += a1*(-qp*s1 - pp*s2);
                    // C2: cell (i,j-1) tri1, slot b: (uW, u00, uSW)
                    e0 = pp*(uSW.x - uW.x);
                    e1 = qm*(u00.y - uW.y);
                    e2 = qm*(u00.x - uW.x) + pp*(uSW.y - uW.y);
                    SIG_();
                    Rx += a2*(qm*s2);
                    Ry += a2*(qm*s1);
                    // C3: cell (i,j-1) tri2, slot b: (u00, uS, uSW)
                    e0 = pp*(uS.x - u00.x);
                    e1 = qm*(uS.y - uSW.y);
                    e2 = qm*(uS.x - uSW.x) + pp*(uS.y - u00.y);
                    SIG_();
                    Rx -= a2*(pp*s0);
                    Ry -= a2*(pp*s2);
                    // C4: cell (i-1,j) tri1, slot c: (uN, uNE, u00)
                    e0 = pm*(u00.x - uN.x);
                    e1 = qp*(uNE.y - uN.y);
                    e2 = qp*(uNE.x - uN.x) + pm*(u00.y - uN.y);
                    SIG_();
                    Rx += a3*(pm*s0);
                    Ry += a3*(pm*s2);
                    // C5: cell (i-1,j) tri2, slot c: (uNE, uE, u00)
                    e0 = pm*(uE.x - uNE.x);
                    e1 = qp*(uE.y - u00.y);
                    e2 = qp*(uE.x - u00.x) + pm*(uE.y - uNE.y);
                    SIG_();
                    Rx -= a3*(qp*s2);
                    Ry -= a3*(qp*s1);
                    // C6: cell (i-1,j-1) tri2, slot d: (uN, u00, uW)
                    e0 = pm*(u00.x - uN.x);
                    e1 = qm*(u00.y - uW.y);
                    e2 = qm*(u00.x - uW.x) + pm*(u00.y - uN.y);
                    SIG_();
                    Rx += a4*(pm*s0 + qm*s2);
                    Ry += a4*(qm*s1 + pm*s2);

                    sR2 += Rx*Rx + Ry*Ry;

                    // energy of owned cell (i,j); E = A - T (clamped rows/cols)
                    const float2 Ec0 = make_float2(A[t][1][k+1].x - T[t][0][k].x,
                                                   A[t][1][k+1].y - T[t][0][k].y);
                    const float2 EcE = make_float2(A[t][1][k+2].x - T[t][0][k+1].x,
                                                   A[t][1][k+2].y - T[t][0][k+1].y);
                    const float2 EcS = make_float2(A[t][2][k+1].x - T[t][1][k].x,
                                                   A[t][2][k+1].y - T[t][1][k].y);
                    const float2 EcD = make_float2(A[t][2][k+2].x - T[t][1][k+1].x,
                                                   A[t][2][k+2].y - T[t][1][k+1].y);

                    e0 = pp*(EcS.x - Ec0.x);
                    e1 = qp*(EcE.y - Ec0.y);
                    e2 = qp*(EcE.x - Ec0.x) + pp*(EcS.y - Ec0.y);
                    SIG_();
                    sEn += a1*(e0*s0 + e1*s1 + e2*s2);

                    e0 = pp*(EcD.x - EcE.x);
                    e1 = qp*(EcD.y - EcS.y);
                    e2 = qp*(EcD.x - EcS.x) + pp*(EcD.y - EcE.y);
                    SIG_();
                    sEn += a1*(e0*s0 + e1*s1 + e2*s2);

                    sA += dxp * dyp;
                }
            }
#undef SIG_
        }
    }

    // ---- block reduction ----
    #pragma unroll
    for (int o = 16; o > 0; o >>= 1) {
        sR2 += __shfl_down_sync(0xffffffffu, sR2, o);
        sEn += __shfl_down_sync(0xffffffffu, sEn, o);
        sA  += __shfl_down_sync(0xffffffffu, sA,  o);
    }
    __shared__ float sh[3][TPB / 32];
    __shared__ bool  amLast;
    const int lane = threadIdx.x & 31;
    const int wid  = threadIdx.x >> 5;
    if (lane == 0) { sh[0][wid] = sR2; sh[1][wid] = sEn; sh[2][wid] = sA; }
    __syncthreads();
    if (threadIdx.x == 0) {
        float r = 0.f, e = 0.f, a = 0.f;
        #pragma unroll
        for (int w = 0; w < TPB / 32; w++) { r += sh[0][w]; e += sh[1][w]; a += sh[2][w]; }
        const int bid = blockIdx.y * gridDim.x + blockIdx.x;
        g_part[bid] = make_float4(r, e, a, 0.f);
        __threadfence();
        unsigned int tk = atomicAdd(&g_ticket, 1u);
        amLast = (tk == (unsigned)(nblocks - 1));
    }
    __syncthreads();

    // ---- last block: final reduce + output + ticket reset ----
    if (amLast) {
        float r = 0.f, e = 0.f, a = 0.f;
        for (int b = threadIdx.x; b < nblocks; b += TPB) {
            float4 p = g_part[b];
            r += p.x; e += p.y; a += p.z;
        }
        #pragma unroll
        for (int o = 16; o > 0; o >>= 1) {
            r += __shfl_down_sync(0xffffffffu, r, o);
            e += __shfl_down_sync(0xffffffffu, e, o);
            a += __shfl_down_sync(0xffffffffu, a, o);
        }
        __syncthreads();
        if (lane == 0) { sh[0][wid] = r; sh[1][wid] = e; sh[2][wid] = a; }
        __syncthreads();
        if (threadIdx.x == 0) {
            r = 0.f; e = 0.f; a = 0.f;
            #pragma unroll
            for (int w = 0; w < TPB / 32; w++) { r += sh[0][w]; e += sh[1][w]; a += sh[2][w]; }
            const double N2 = 2.0 * (double)g * (double)g;
            double Ad = (double)a;
            if (Ad < 1e-30) Ad = 1e-30;
            out[0] = (float)(0.1 * ((double)r / N2) + 0.1 * ((double)e / Ad));
            g_ticket = 0;   // self-reset for next graph replay
        }
    }
}

extern "C" void kernel_launch(void* const* d_in, const int* in_sizes, int n_in,
                              void* d_out, int out_size) {
    const float2* up     = (const float2*)d_in[0];  // u_pred (N,2) f32
    const float2* ut     = (const float2*)d_in[1];  // u_true (N,2) f32
    const float2* coords = (const float2*)d_in[2];  // coords (N,2) f32
    // d_in[3] = elems — mesh structure is analytic; unused.

    int N = in_sizes[0] / 2;
    int g = (int)(sqrt((double)N) + 0.5);
    float h  = 1.0f / (float)(g - 1);
    float h2 = h * h;

    // half-row span, rounded up to a whole tile; tile0 covers [0,half),
    // tile1 covers [half, 2*half) ⊇ [0,g)
    int half = ((g + 1) / 2 + NPT - 1) / NPT * NPT;
    int gx   = (half + TPB * NPT - 1) / (TPB * NPT);

    dim3 grid(gx, g);
    int nblocks = grid.x * grid.y;
    if (nblocks > MAX_BLOCKS) nblocks = MAX_BLOCKS;  // (never hit for G<=2048)
    pino_dual_kernel<<<grid, TPB>>>(up, ut, coords, (float*)d_out, g, nblocks, h2, half);
}